// round 1
// baseline (speedup 1.0000x reference)
#include <cuda_runtime.h>

#define N_NODES 16384
#define N_FEAT  16384
#define EMBED   64
#define BATCH   4096
#define N_EDGES 524288

// ---------------- device scratch (no dynamic allocation allowed) ----------------
__device__ int   g_is64;
__device__ int   g_degcnt[N_NODES];
__device__ float g_dinv[N_NODES];
__device__ float g_xw[N_NODES * EMBED];    // X @ W_gcn
__device__ float g_agg[N_NODES * EMBED];   // GCN output embeddings

// Read index i from an array that is either int64 or int32 (runtime-detected).
__device__ __forceinline__ int load_idx(const void* p, long long i, int is64) {
    if (is64) return (int)(((const long long*)p)[i]);
    return ((const int*)p)[i];
}

// ---------------- dtype detection ----------------
// If x is int64: every 8-byte word is a valid node index in [0, N_NODES).
// If x is int32: an 8-byte word packs two random indices -> value >= 2^32 unless
// the high half is 0 (prob 1/16384 per word; 64 words -> ~0 false positive).
__global__ void k_detect(const void* __restrict__ x) {
    const long long* p = (const long long*)x;
    int ok = 1;
    for (int i = 0; i < 64; i++) {
        long long v = p[i];
        if (v < 0 || v >= N_NODES) { ok = 0; break; }
    }
    g_is64 = ok;
}

// ---------------- degree / normalization ----------------
__global__ void k_deg_zero() {
    int i = blockIdx.x * blockDim.x + threadIdx.x;
    g_degcnt[i] = 0;
}

__global__ void k_deg_count(const void* __restrict__ edges) {
    int e = blockIdx.x * blockDim.x + threadIdx.x;
    int is64 = g_is64;
    int dst = load_idx(edges, (long long)N_EDGES + e, is64);
    atomicAdd(&g_degcnt[dst], 1);
}

__global__ void k_dinv() {
    int i = blockIdx.x * blockDim.x + threadIdx.x;
    // self-loop contributes +1; deg >= 1 always, so no zero guard needed
    g_dinv[i] = rsqrtf(1.0f + (float)g_degcnt[i]);
}

// ---------------- GEMM: g_xw = X[16384,16384] @ W[16384,64] ----------------
// Block: 256 threads computes a 64-row x 64-col output tile. K chunked by 64.
// Thread tile: 4 rows x 4 cols (float4 on the col axis).
__global__ void __launch_bounds__(256) k_gemm(const float* __restrict__ X,
                                              const float* __restrict__ W) {
    __shared__ float Xs[64][65];   // +1 pad: conflict-free Xs[r][k] reads
    __shared__ float Ws[64][64];   // unpadded: aligned float4 rows

    const int tid = threadIdx.x;
    const int tx = tid & 15;       // col quad (0..15) -> cols tx*4 .. tx*4+3
    const int ty = tid >> 4;       // row group (0..15) -> rows ty + 16*j
    const long long rb = (long long)blockIdx.x * 64;

    float acc[4][4] = {};

    for (int k0 = 0; k0 < N_FEAT; k0 += 64) {
#pragma unroll
        for (int j = 0; j < 4; j++) {
            int r = ty + 16 * j;
            // X tile load: 64 rows x 64 k, streamed (no reuse across blocks)
            float4 v = __ldcs((const float4*)(X + (rb + r) * (long long)N_FEAT + k0 + tx * 4));
            Xs[r][tx * 4 + 0] = v.x;
            Xs[r][tx * 4 + 1] = v.y;
            Xs[r][tx * 4 + 2] = v.z;
            Xs[r][tx * 4 + 3] = v.w;
            // W tile load: rows k0..k0+63 (W is L2-resident, 4 MB)
            float4 w = *(const float4*)(W + (long long)(k0 + r) * EMBED + tx * 4);
            *(float4*)(&Ws[r][tx * 4]) = w;
        }
        __syncthreads();

#pragma unroll
        for (int k = 0; k < 64; k++) {
            float4 b = *(const float4*)(&Ws[k][tx * 4]);
#pragma unroll
            for (int j = 0; j < 4; j++) {
                float a = Xs[ty + 16 * j][k];
                acc[j][0] += a * b.x;
                acc[j][1] += a * b.y;
                acc[j][2] += a * b.z;
                acc[j][3] += a * b.w;
            }
        }
        __syncthreads();
    }

#pragma unroll
    for (int j = 0; j < 4; j++) {
        long long r = rb + ty + 16 * j;
        *(float4*)(&g_xw[r * EMBED + tx * 4]) =
            make_float4(acc[j][0], acc[j][1], acc[j][2], acc[j][3]);
    }
}

// ---------------- aggregation init: self-loop term + bias ----------------
__global__ void k_agg_init(const float* __restrict__ b_gcn) {
    int i = blockIdx.x * blockDim.x + threadIdx.x;   // over N_NODES*EMBED
    int n = i >> 6;
    int d = i & 63;
    float di = g_dinv[n];
    g_agg[i] = g_xw[i] * di * di + b_gcn[d];
}

// ---------------- edge aggregation: agg[dst] += xw[src] * dinv[src]*dinv[dst] ----
__global__ void k_agg_edges(const void* __restrict__ edges) {
    long long t = (long long)blockIdx.x * blockDim.x + threadIdx.x;
    int e = (int)(t >> 6);
    int d = (int)(t & 63);
    int is64 = g_is64;
    int src = load_idx(edges, e, is64);
    int dst = load_idx(edges, (long long)N_EDGES + e, is64);
    float nrm = g_dinv[src] * g_dinv[dst];
    atomicAdd(&g_agg[dst * EMBED + d], g_xw[src * EMBED + d] * nrm);
}

// ---------------- final head: out[b] = w_lin[i0]+w_lin[i1]+b_lin + dot(emb0, emb1)
// (2-field FM pairwise interaction reduces exactly to the dot product)
__global__ void k_final(const void* __restrict__ x,
                        const float* __restrict__ w_lin,
                        const float* __restrict__ b_lin,
                        float* __restrict__ out) {
    int b = blockIdx.x * (blockDim.x >> 5) + (threadIdx.x >> 5);
    int lane = threadIdx.x & 31;
    if (b >= BATCH) return;
    int is64 = g_is64;
    int i0 = load_idx(x, 2LL * b,     is64);
    int i1 = load_idx(x, 2LL * b + 1, is64);
    const float* e0 = &g_agg[(long long)i0 * EMBED];
    const float* e1 = &g_agg[(long long)i1 * EMBED];
    float s = e0[lane] * e1[lane] + e0[lane + 32] * e1[lane + 32];
#pragma unroll
    for (int o = 16; o; o >>= 1) s += __shfl_xor_sync(0xFFFFFFFFu, s, o);
    if (lane == 0) out[b] = s + w_lin[i0] + w_lin[i1] + b_lin[0];
}

// ---------------- launch ----------------
extern "C" void kernel_launch(void* const* d_in, const int* in_sizes, int n_in,
                              void* d_out, int out_size) {
    const void*  x     = d_in[0];                  // [4096,2] int32/int64
    const float* X     = (const float*)d_in[1];    // [16384,16384]
    const void*  edges = d_in[2];                  // [2,524288] int32/int64
    const float* Wg    = (const float*)d_in[3];    // [16384,64]
    const float* bg    = (const float*)d_in[4];    // [64]
    const float* wl    = (const float*)d_in[5];    // [16384,1]
    const float* bl    = (const float*)d_in[6];    // [1]
    float* out = (float*)d_out;                    // [4096]

    k_detect<<<1, 1>>>(x);
    k_deg_zero<<<N_NODES / 256, 256>>>();
    k_deg_count<<<N_EDGES / 256, 256>>>(edges);
    k_dinv<<<N_NODES / 256, 256>>>();
    k_gemm<<<N_NODES / 64, 256>>>(X, Wg);
    k_agg_init<<<(N_NODES * EMBED) / 256, 256>>>(bg);
    k_agg_edges<<<(int)(((long long)N_EDGES * EMBED) / 256), 256>>>(edges);
    k_final<<<BATCH / 8, 256>>>(x, wl, bl, out);
}

// round 3
// speedup vs baseline: 3.4816x; 3.4816x over previous
#include <cuda_runtime.h>
#include <cstdint>

#define N_NODES 16384
#define N_FEAT  16384
#define EMBED   64
#define BATCH   4096
#define N_EDGES 524288

#define MT   128                 // CTA M tile
#define KT   32                  // K tile (floats)
#define NITR (N_FEAT / KT)       // 512
#define STAGE_BYTES 24576        // A 16KB + B 8KB
#define B_OFF 16384

// ---------------- device scratch ----------------
__device__ int   g_is64;
__device__ int   g_degcnt[N_NODES];
__device__ int   g_need[N_NODES];
__device__ float g_dinv[N_NODES];
__device__ __align__(16) float g_wt[EMBED * N_FEAT];   // W^T, tf32-rounded
__device__ __align__(16) float g_xw[N_NODES * EMBED];  // X @ W_gcn
__device__ __align__(16) float g_agg[N_NODES * EMBED]; // GCN output

// ---------------- helpers ----------------
__device__ __forceinline__ uint32_t f2tf32(float f) {
    uint32_t r;
    asm("cvt.rna.tf32.f32 %0, %1;" : "=r"(r) : "f"(f));
    return r;
}
__device__ __forceinline__ int load_idx(const void* p, long long i, int is64) {
    if (is64) return (int)(((const long long*)p)[i]);
    return ((const int*)p)[i];
}

#define MMA(d, a0, a1, a2, a3, b0, b1)                                          \
    asm volatile(                                                                \
        "mma.sync.aligned.m16n8k8.row.col.f32.tf32.tf32.f32 "                    \
        "{%0,%1,%2,%3}, {%4,%5,%6,%7}, {%8,%9}, {%0,%1,%2,%3};"                  \
        : "+f"((d)[0]), "+f"((d)[1]), "+f"((d)[2]), "+f"((d)[3])                 \
        : "r"(a0), "r"(a1), "r"(a2), "r"(a3), "r"(b0), "r"(b1))

// ---------------- dtype detection ----------------
__global__ void k_detect(const void* __restrict__ x) {
    const long long* p = (const long long*)x;
    int ok = 1;
    for (int i = 0; i < 64; i++) {
        long long v = p[i];
        if (v < 0 || v >= N_NODES) { ok = 0; break; }
    }
    g_is64 = ok;
}

// ---------------- degree / need-mask / normalization ----------------
__global__ void k_zero() {
    int i = blockIdx.x * blockDim.x + threadIdx.x;
    g_degcnt[i] = 0;
    g_need[i] = 0;
}
__global__ void k_deg_count(const void* __restrict__ edges) {
    int e = blockIdx.x * blockDim.x + threadIdx.x;
    int dst = load_idx(edges, (long long)N_EDGES + e, g_is64);
    atomicAdd(&g_degcnt[dst], 1);
}
__global__ void k_mark(const void* __restrict__ x) {
    int t = blockIdx.x * blockDim.x + threadIdx.x;
    int i = load_idx(x, t, g_is64);
    g_need[i] = 1;
}
__global__ void k_dinv() {
    int i = blockIdx.x * blockDim.x + threadIdx.x;
    g_dinv[i] = rsqrtf(1.0f + (float)g_degcnt[i]);
}

// ---------------- W transpose + tf32 round: g_wt[n][k] = tf32(W[k][n]) --------
__global__ void k_prep_wt(const float* __restrict__ W) {
    int t = blockIdx.x * blockDim.x + threadIdx.x;
    int n = t >> 14;
    int k = t & (N_FEAT - 1);
    g_wt[t] = __uint_as_float(f2tf32(W[(long long)k * EMBED + n]));
}

// ---------------- tf32 mma.sync GEMM: g_xw = X @ W ----------------
// CTA: 128x64, 256 thr (8 warps). Warp (wid): M-block (wid&1)*64, N-block
// ((wid>>1)&1)*32, K-half wid>>2 (ksteps 2*kh .. 2*kh+1). Pair epilogue merge.
// smem swizzle: 16B chunk c of row i stored at chunk (c ^ (i&7)).

#define LDG_TILE(bufA, bufB, kt)                                                \
    do {                                                                        \
        _Pragma("unroll")                                                       \
        for (int ss = 0; ss < 4; ss++)                                          \
            bufA[ss] = __ldcs((const float4*)(Abase[ss] + (kt) * KT));          \
        _Pragma("unroll")                                                       \
        for (int ss = 0; ss < 2; ss++)                                          \
            bufB[ss] = *(const float4*)(Bbase[ss] + (kt) * KT);                 \
    } while (0)

#define STS_TILE(bufA, bufB, sbase)                                             \
    do {                                                                        \
        _Pragma("unroll")                                                       \
        for (int ss = 0; ss < 4; ss++) {                                        \
            float4 v = bufA[ss];                                                \
            uint4 u = make_uint4(f2tf32(v.x), f2tf32(v.y),                      \
                                 f2tf32(v.z), f2tf32(v.w));                     \
            int i = r0 + 32 * ss;                                               \
            *(uint4*)((sbase) + (i * 8 + (q ^ (i & 7))) * 16) = u;              \
        }                                                                       \
        _Pragma("unroll")                                                       \
        for (int ss = 0; ss < 2; ss++) {                                        \
            int i = r0 + 32 * ss;                                               \
            *(float4*)((sbase) + B_OFF + (i * 8 + (q ^ (i & 7))) * 16) =        \
                bufB[ss];                                                       \
        }                                                                       \
    } while (0)

#define COMPUTE_TILE(sbase)                                                     \
    do {                                                                        \
        _Pragma("unroll")                                                       \
        for (int ks = 0; ks < 2; ks++) {                                        \
            const int c0 = (khalf * 2 + ks) * 2;                                \
            uint32_t bf[4][2];                                                  \
            _Pragma("unroll")                                                   \
            for (int nf = 0; nf < 4; nf++) {                                    \
                int o = nrow[nf] + ((c0 ^ nx[nf]) << 4);                        \
                bf[nf][0] = *(const uint32_t*)((sbase) + o);                    \
                bf[nf][1] = *(const uint32_t*)((sbase) + (o ^ 16));             \
            }                                                                   \
            _Pragma("unroll")                                                   \
            for (int mf = 0; mf < 4; mf++) {                                    \
                int o = mrow[mf] + ((c0 ^ mx[mf]) << 4);                        \
                uint32_t a0 = *(const uint32_t*)((sbase) + o);                  \
                uint32_t a1 = *(const uint32_t*)((sbase) + o + 1024);           \
                uint32_t a2 = *(const uint32_t*)((sbase) + (o ^ 16));           \
                uint32_t a3 = *(const uint32_t*)((sbase) + (o ^ 16) + 1024);    \
                _Pragma("unroll")                                               \
                for (int nf = 0; nf < 4; nf++)                                  \
                    MMA(acc[mf][nf], a0, a1, a2, a3, bf[nf][0], bf[nf][1]);     \
            }                                                                   \
        }                                                                       \
    } while (0)

__global__ void __launch_bounds__(256, 1) k_gemm_mma(const float* __restrict__ X) {
    __shared__ __align__(16) char smem[2 * STAGE_BYTES];   // 48KB

    const int tid  = threadIdx.x;
    const int wid  = tid >> 5;
    const int lane = tid & 31;
    const long long rb = (long long)blockIdx.x * MT;

    // producer addressing
    const int q  = tid & 7;
    const int r0 = tid >> 3;
    const float* Abase[4];
    const float* Bbase[2];
#pragma unroll
    for (int ss = 0; ss < 4; ss++)
        Abase[ss] = X + (rb + r0 + 32 * ss) * (long long)N_FEAT + q * 4;
#pragma unroll
    for (int ss = 0; ss < 2; ss++)
        Bbase[ss] = g_wt + (long long)(r0 + 32 * ss) * N_FEAT + q * 4;

    // consumer addressing
    const int mbase = (wid & 1) * 64;
    const int nbase = ((wid >> 1) & 1) * 32;
    const int khalf = wid >> 2;
    const int tf = lane >> 2, tk = lane & 3;
    int mrow[4], mx[4], nrow[4], nx[4];
#pragma unroll
    for (int mf = 0; mf < 4; mf++) {
        int im = mbase + mf * 16 + tf;
        mrow[mf] = im * 128 + tk * 4;
        mx[mf] = im & 7;
    }
#pragma unroll
    for (int nf = 0; nf < 4; nf++) {
        int nn = nbase + nf * 8 + tf;
        nrow[nf] = B_OFF + nn * 128 + tk * 4;
        nx[nf] = nn & 7;
    }

    float acc[4][4][4] = {};
    float4 bufA0[4], bufB0[2], bufA1[4], bufB1[2];

    // prologue
    LDG_TILE(bufA0, bufB0, 0);
    LDG_TILE(bufA1, bufB1, 1);
    STS_TILE(bufA0, bufB0, smem);
    __syncthreads();

    for (int kt = 0; kt < NITR; kt += 2) {
        // even iter: stage0 holds t_kt (bufA0 staged), bufA1 holds t_{kt+1}
        if (kt + 2 < NITR) LDG_TILE(bufA0, bufB0, kt + 2);
        COMPUTE_TILE(smem);
        STS_TILE(bufA1, bufB1, smem + STAGE_BYTES);
        __syncthreads();
        // odd iter
        if (kt + 3 < NITR) LDG_TILE(bufA1, bufB1, kt + 3);
        COMPUTE_TILE(smem + STAGE_BYTES);
        if (kt + 2 < NITR) STS_TILE(bufA0, bufB0, smem);
        __syncthreads();
    }

    // ---- epilogue: merge K-halves (warp w += warp w+4), write out ----
    if (khalf == 1) {
        float4* st = (float4*)smem;
#pragma unroll
        for (int mf = 0; mf < 4; mf++)
#pragma unroll
            for (int nf = 0; nf < 4; nf++)
                st[(wid - 4) * 512 + (mf * 4 + nf) * 32 + lane] =
                    make_float4(acc[mf][nf][0], acc[mf][nf][1],
                                acc[mf][nf][2], acc[mf][nf][3]);
    }
    __syncthreads();
    if (khalf == 0) {
        const float4* ld = (const float4*)smem;
#pragma unroll
        for (int mf = 0; mf < 4; mf++) {
#pragma unroll
            for (int nf = 0; nf < 4; nf++) {
                float4 m = ld[wid * 512 + (mf * 4 + nf) * 32 + lane];
                long long row = rb + mbase + mf * 16 + tf;
                int col = nbase + nf * 8 + 2 * tk;
                float2* o0 = (float2*)(g_xw + row * EMBED + col);
                float2* o1 = (float2*)(g_xw + (row + 8) * EMBED + col);
                *o0 = make_float2(acc[mf][nf][0] + m.x, acc[mf][nf][1] + m.y);
                *o1 = make_float2(acc[mf][nf][2] + m.z, acc[mf][nf][3] + m.w);
            }
        }
    }
}

// ---------------- aggregation init: self-loop term + bias ----------------
__global__ void k_agg_init(const float* __restrict__ b_gcn) {
    int i = blockIdx.x * blockDim.x + threadIdx.x;
    int n = i >> 6;
    int d = i & 63;
    float di = g_dinv[n];
    g_agg[i] = g_xw[i] * di * di + b_gcn[d];
}

// ---------------- edge aggregation (filtered by needed dst) ----------------
__global__ void k_agg_edges(const void* __restrict__ edges) {
    long long t = (long long)blockIdx.x * blockDim.x + threadIdx.x;
    int e = (int)(t >> 4);
    int qd = (int)(t & 15);
    int is64 = g_is64;
    int dst = load_idx(edges, (long long)N_EDGES + e, is64);
    if (!g_need[dst]) return;
    int src = load_idx(edges, e, is64);
    float nrm = g_dinv[src] * g_dinv[dst];
    float4 v = ((const float4*)(g_xw + (long long)src * EMBED))[qd];
    float* o = g_agg + (long long)dst * EMBED + qd * 4;
    atomicAdd(o + 0, v.x * nrm);
    atomicAdd(o + 1, v.y * nrm);
    atomicAdd(o + 2, v.z * nrm);
    atomicAdd(o + 3, v.w * nrm);
}

// ---------------- final head: lin + dot(emb0, emb1) ----------------
__global__ void k_final(const void* __restrict__ x,
                        const float* __restrict__ w_lin,
                        const float* __restrict__ b_lin,
                        float* __restrict__ out) {
    int b = blockIdx.x * (blockDim.x >> 5) + (threadIdx.x >> 5);
    int lane = threadIdx.x & 31;
    if (b >= BATCH) return;
    int is64 = g_is64;
    int i0 = load_idx(x, 2LL * b, is64);
    int i1 = load_idx(x, 2LL * b + 1, is64);
    const float* e0 = &g_agg[(long long)i0 * EMBED];
    const float* e1 = &g_agg[(long long)i1 * EMBED];
    float s = e0[lane] * e1[lane] + e0[lane + 32] * e1[lane + 32];
#pragma unroll
    for (int o = 16; o; o >>= 1) s += __shfl_xor_sync(0xFFFFFFFFu, s, o);
    if (lane == 0) out[b] = s + w_lin[i0] + w_lin[i1] + b_lin[0];
}

// ---------------- launch ----------------
extern "C" void kernel_launch(void* const* d_in, const int* in_sizes, int n_in,
                              void* d_out, int out_size) {
    const void*  x     = d_in[0];
    const float* X     = (const float*)d_in[1];
    const void*  edges = d_in[2];
    const float* Wg    = (const float*)d_in[3];
    const float* bg    = (const float*)d_in[4];
    const float* wl    = (const float*)d_in[5];
    const float* bl    = (const float*)d_in[6];
    float* out = (float*)d_out;

    k_detect<<<1, 1>>>(x);
    k_zero<<<N_NODES / 256, 256>>>();
    k_deg_count<<<N_EDGES / 256, 256>>>(edges);
    k_mark<<<(2 * BATCH) / 256, 256>>>(x);
    k_dinv<<<N_NODES / 256, 256>>>();
    k_prep_wt<<<(EMBED * N_FEAT) / 256, 256>>>(Wg);
    k_gemm_mma<<<N_NODES / MT, 256>>>(X);
    k_agg_init<<<(N_NODES * EMBED) / 256, 256>>>(bg);
    k_agg_edges<<<(int)(((long long)N_EDGES * 16) / 256), 256>>>(edges);
    k_final<<<BATCH / 8, 256>>>(x, wl, bl, out);
}

// round 4
// speedup vs baseline: 4.5185x; 1.2978x over previous
#include <cuda_runtime.h>
#include <cstdint>

#define N_NODES 16384
#define N_FEAT  16384
#define EMBED   64
#define BATCH   4096
#define N_EDGES 524288

#define MT    128
#define KT    32
#define NITR  (N_FEAT / KT)          // 512
#define ABYTES (MT * KT * 4)         // 16384
#define BBYTES (EMBED * KT * 4)      // 8192
#define STG   (ABYTES + BBYTES)      // 24576
#define NSTAGE 4
#define GEMM_SMEM (NSTAGE * STG)     // 98304

// ---------------- device scratch ----------------
__device__ int   g_is64;
__device__ int   g_degcnt[N_NODES];
__device__ int   g_need[N_NODES];
__device__ float g_dinv[N_NODES];
__device__ int   g_nsel;
__device__ int   g_sel_src[N_EDGES];
__device__ int   g_sel_dst[N_EDGES];
__device__ float g_sel_nrm[N_EDGES];
__device__ __align__(16) float g_wt[EMBED * N_FEAT];   // W^T, RNA-rounded to tf32
__device__ __align__(16) float g_xw[N_NODES * EMBED];
__device__ __align__(16) float g_agg[N_NODES * EMBED];

// ---------------- helpers ----------------
__device__ __forceinline__ uint32_t f2tf32(float f) {
    uint32_t r;
    asm("cvt.rna.tf32.f32 %0, %1;" : "=r"(r) : "f"(f));
    return r;
}
__device__ __forceinline__ int load_idx(const void* p, long long i, int is64) {
    if (is64) return (int)(((const long long*)p)[i]);
    return ((const int*)p)[i];
}
__device__ __forceinline__ void cp16(uint32_t dst, const void* src) {
    asm volatile("cp.async.cg.shared.global [%0], [%1], 16;" :: "r"(dst), "l"(src) : "memory");
}
__device__ __forceinline__ void cp_commit() {
    asm volatile("cp.async.commit_group;" ::: "memory");
}
__device__ __forceinline__ void cp_wait3() {
    asm volatile("cp.async.wait_group 3;" ::: "memory");
}
__device__ __forceinline__ uint32_t lds32(uint32_t a) {
    uint32_t v;
    asm volatile("ld.shared.b32 %0, [%1];" : "=r"(v) : "r"(a));
    return v;
}

#define MMA(d, a0, a1, a2, a3, b0, b1)                                          \
    asm volatile(                                                                \
        "mma.sync.aligned.m16n8k8.row.col.f32.tf32.tf32.f32 "                    \
        "{%0,%1,%2,%3}, {%4,%5,%6,%7}, {%8,%9}, {%0,%1,%2,%3};"                  \
        : "+f"((d)[0]), "+f"((d)[1]), "+f"((d)[2]), "+f"((d)[3])                 \
        : "r"(a0), "r"(a1), "r"(a2), "r"(a3), "r"(b0), "r"(b1))

// ---------------- small kernels ----------------
__global__ void k_detect(const void* __restrict__ x) {
    const long long* p = (const long long*)x;
    int ok = 1;
    for (int i = 0; i < 64; i++) {
        long long v = p[i];
        if (v < 0 || v >= N_NODES) { ok = 0; break; }
    }
    g_is64 = ok;
}
__global__ void k_zero() {
    int i = blockIdx.x * blockDim.x + threadIdx.x;
    g_degcnt[i] = 0;
    g_need[i] = 0;
    if (i == 0) g_nsel = 0;
}
__global__ void k_deg_count(const void* __restrict__ edges) {
    int e = blockIdx.x * blockDim.x + threadIdx.x;
    int dst = load_idx(edges, (long long)N_EDGES + e, g_is64);
    atomicAdd(&g_degcnt[dst], 1);
}
__global__ void k_mark(const void* __restrict__ x) {
    int t = blockIdx.x * blockDim.x + threadIdx.x;
    int i = load_idx(x, t, g_is64);
    g_need[i] = 1;
}
__global__ void k_dinv() {
    int i = blockIdx.x * blockDim.x + threadIdx.x;
    g_dinv[i] = rsqrtf(1.0f + (float)g_degcnt[i]);
}
__global__ void k_prep_wt(const float* __restrict__ W) {
    int t = blockIdx.x * blockDim.x + threadIdx.x;
    int n = t >> 14;
    int k = t & (N_FEAT - 1);
    g_wt[t] = __uint_as_float(f2tf32(W[(long long)k * EMBED + n]));
}

// ---------------- GEMM: g_xw = X[16384,16384] @ W[16384,64] (tf32 mma) --------
// CTA 128x64, 256 thr. Warp w: mhalf=w&1 (64 rows), khalf=w>>1 (k8-slice of KT).
// Each warp computes full 64x64 over its k8 slice -> 4-way k merge in epilogue.
// 4-stage cp.async pipeline; smem chunk-swizzled (16B chunk c of row i -> c^(i&7)).
__global__ void __launch_bounds__(256, 1) k_gemm_mma(const float* __restrict__ X) {
    extern __shared__ __align__(16) char smem[];
    const uint32_t sb = (uint32_t)__cvta_generic_to_shared(smem);

    const int tid  = threadIdx.x;
    const int wid  = tid >> 5;
    const int lane = tid & 31;
    const int mhalf = wid & 1;
    const int khalf = wid >> 1;          // 0..3
    const int tf = lane >> 2;            // 0..7
    const int tk = lane & 3;             // 0..3
    const long long rb = (long long)blockIdx.x * MT;

    // ---- producer addressing: thread t copies 4 A-chunks + 2 B-chunks / stage
    const int q  = tid & 7;              // 16B chunk in 128B row
    const int r0 = tid >> 3;             // 0..31
    const uint32_t dsw = (uint32_t)((q ^ (r0 & 7)) << 4);
    uint32_t adst[4], bdst[2];
    const float* asrc[4];
    const float* bsrc[2];
#pragma unroll
    for (int i = 0; i < 4; i++) {
        adst[i] = (uint32_t)((r0 + 32 * i) * 128) + dsw;
        asrc[i] = X + (rb + r0 + 32 * i) * (long long)N_FEAT + q * 4;
    }
#pragma unroll
    for (int i = 0; i < 2; i++) {
        bdst[i] = (uint32_t)(ABYTES + (r0 + 32 * i) * 128) + dsw;
        bsrc[i] = g_wt + (long long)(r0 + 32 * i) * N_FEAT + q * 4;
    }

    // ---- consumer addressing
    uint32_t ao[4], bo[8];
    const uint32_t csw = (uint32_t)(((2 * khalf) ^ tf) << 4) + (uint32_t)(tk * 4);
#pragma unroll
    for (int mf = 0; mf < 4; mf++)
        ao[mf] = (uint32_t)((mhalf * 64 + mf * 16 + tf) * 128) + csw;
#pragma unroll
    for (int nf = 0; nf < 8; nf++)
        bo[nf] = (uint32_t)(ABYTES + (nf * 8 + tf) * 128) + csw;

    float acc[4][8][4] = {};

    // ---- prologue: stages 0..2
#pragma unroll
    for (int s = 0; s < NSTAGE - 1; s++) {
        const uint32_t st = sb + s * STG;
        const int ko = s * KT;
#pragma unroll
        for (int i = 0; i < 4; i++) cp16(st + adst[i], asrc[i] + ko);
#pragma unroll
        for (int i = 0; i < 2; i++) cp16(st + bdst[i], bsrc[i] + ko);
        cp_commit();
    }

    for (int kt = 0; kt < NITR; kt++) {
        if (kt + NSTAGE - 1 < NITR) {
            const int s = (kt + NSTAGE - 1) & (NSTAGE - 1);
            const uint32_t st = sb + s * STG;
            const int ko = (kt + NSTAGE - 1) * KT;
#pragma unroll
            for (int i = 0; i < 4; i++) cp16(st + adst[i], asrc[i] + ko);
#pragma unroll
            for (int i = 0; i < 2; i++) cp16(st + bdst[i], bsrc[i] + ko);
        }
        cp_commit();                     // empty groups at tail keep count invariant
        cp_wait3();
        __syncthreads();

        const uint32_t st = sb + (kt & (NSTAGE - 1)) * STG;
        uint32_t bf0[8], bf1[8];
#pragma unroll
        for (int nf = 0; nf < 8; nf++) {
            bf0[nf] = lds32(st + bo[nf]);
            bf1[nf] = lds32(st + (bo[nf] ^ 16));
        }
#pragma unroll
        for (int mf = 0; mf < 4; mf++) {
            uint32_t a0 = f2tf32(__uint_as_float(lds32(st + ao[mf])));
            uint32_t a1 = f2tf32(__uint_as_float(lds32(st + ao[mf] + 1024)));
            uint32_t a2 = f2tf32(__uint_as_float(lds32(st + (ao[mf] ^ 16))));
            uint32_t a3 = f2tf32(__uint_as_float(lds32(st + (ao[mf] ^ 16) + 1024)));
#pragma unroll
            for (int nf = 0; nf < 8; nf++)
                MMA(acc[mf][nf], a0, a1, a2, a3, bf0[nf], bf1[nf]);
        }
        __syncthreads();
    }

    // ---- epilogue: merge 4 khalf partials via smem (reuses 96KB pipeline smem)
    if (khalf != 0) {
        const int p = (khalf - 1) * 2 + mhalf;
        float4* stp = (float4*)(smem + p * 16384);
#pragma unroll
        for (int mf = 0; mf < 4; mf++)
#pragma unroll
            for (int nf = 0; nf < 8; nf++)
                stp[(mf * 8 + nf) * 32 + lane] =
                    make_float4(acc[mf][nf][0], acc[mf][nf][1],
                                acc[mf][nf][2], acc[mf][nf][3]);
    }
    __syncthreads();
    if (khalf == 0) {
        const float4* p0 = (const float4*)(smem + (0 + mhalf) * 16384);
        const float4* p1 = (const float4*)(smem + (2 + mhalf) * 16384);
        const float4* p2 = (const float4*)(smem + (4 + mhalf) * 16384);
#pragma unroll
        for (int mf = 0; mf < 4; mf++) {
#pragma unroll
            for (int nf = 0; nf < 8; nf++) {
                const int o = (mf * 8 + nf) * 32 + lane;
                float4 u = p0[o], v = p1[o], w = p2[o];
                float c0 = acc[mf][nf][0] + u.x + v.x + w.x;
                float c1 = acc[mf][nf][1] + u.y + v.y + w.y;
                float c2 = acc[mf][nf][2] + u.z + v.z + w.z;
                float c3 = acc[mf][nf][3] + u.w + v.w + w.w;
                long long row = rb + mhalf * 64 + mf * 16 + tf;
                int col = nf * 8 + 2 * tk;
                *(float2*)(g_xw + row * EMBED + col)       = make_float2(c0, c1);
                *(float2*)(g_xw + (row + 8) * EMBED + col) = make_float2(c2, c3);
            }
        }
    }
}

// ---------------- edge compaction: keep edges whose dst is referenced --------
__global__ void k_edge_sel(const void* __restrict__ edges) {
    int e = blockIdx.x * blockDim.x + threadIdx.x;
    int is64 = g_is64;
    int dst = load_idx(edges, (long long)N_EDGES + e, is64);
    if (!g_need[dst]) return;
    int src = load_idx(edges, e, is64);
    int pos = atomicAdd(&g_nsel, 1);
    g_sel_src[pos] = src;
    g_sel_dst[pos] = dst;
    g_sel_nrm[pos] = g_dinv[src] * g_dinv[dst];
}

// ---------------- aggregation init: self-loop term + bias ----------------
__global__ void k_agg_init(const float* __restrict__ b_gcn) {
    int i = blockIdx.x * blockDim.x + threadIdx.x;
    int n = i >> 6;
    int d = i & 63;
    float di = g_dinv[n];
    g_agg[i] = g_xw[i] * di * di + b_gcn[d];
}

// ---------------- edge aggregation over compacted list ----------------
__global__ void k_agg_edges() {
    long long t = (long long)blockIdx.x * blockDim.x + threadIdx.x;
    int e = (int)(t >> 4);
    if (e >= g_nsel) return;
    int qd = (int)(t & 15);
    int src = g_sel_src[e];
    int dst = g_sel_dst[e];
    float nrm = g_sel_nrm[e];
    float4 v = ((const float4*)(g_xw + (long long)src * EMBED))[qd];
    float* o = g_agg + (long long)dst * EMBED + qd * 4;
    atomicAdd(o + 0, v.x * nrm);
    atomicAdd(o + 1, v.y * nrm);
    atomicAdd(o + 2, v.z * nrm);
    atomicAdd(o + 3, v.w * nrm);
}

// ---------------- final head: lin + dot(emb0, emb1) ----------------
__global__ void k_final(const void* __restrict__ x,
                        const float* __restrict__ w_lin,
                        const float* __restrict__ b_lin,
                        float* __restrict__ out) {
    int b = blockIdx.x * (blockDim.x >> 5) + (threadIdx.x >> 5);
    int lane = threadIdx.x & 31;
    if (b >= BATCH) return;
    int is64 = g_is64;
    int i0 = load_idx(x, 2LL * b, is64);
    int i1 = load_idx(x, 2LL * b + 1, is64);
    const float* e0 = &g_agg[(long long)i0 * EMBED];
    const float* e1 = &g_agg[(long long)i1 * EMBED];
    float s = e0[lane] * e1[lane] + e0[lane + 32] * e1[lane + 32];
#pragma unroll
    for (int o = 16; o; o >>= 1) s += __shfl_xor_sync(0xFFFFFFFFu, s, o);
    if (lane == 0) out[b] = s + w_lin[i0] + w_lin[i1] + b_lin[0];
}

// ---------------- launch (GEMM placed 4th: the ncu-profiled slot) -------------
extern "C" void kernel_launch(void* const* d_in, const int* in_sizes, int n_in,
                              void* d_out, int out_size) {
    const void*  x     = d_in[0];
    const float* X     = (const float*)d_in[1];
    const void*  edges = d_in[2];
    const float* Wg    = (const float*)d_in[3];
    const float* bg    = (const float*)d_in[4];
    const float* wl    = (const float*)d_in[5];
    const float* bl    = (const float*)d_in[6];
    float* out = (float*)d_out;

    cudaFuncSetAttribute(k_gemm_mma, cudaFuncAttributeMaxDynamicSharedMemorySize, GEMM_SMEM);

    k_detect<<<1, 1>>>(x);                                      // 1
    k_prep_wt<<<(EMBED * N_FEAT) / 256, 256>>>(Wg);             // 2
    k_zero<<<N_NODES / 256, 256>>>();                           // 3
    k_gemm_mma<<<N_NODES / MT, 256, GEMM_SMEM>>>(X);            // 4 <- profiled
    k_deg_count<<<N_EDGES / 256, 256>>>(edges);                 // 5
    k_mark<<<(2 * BATCH) / 256, 256>>>(x);                      // 6
    k_dinv<<<N_NODES / 256, 256>>>();                           // 7
    k_edge_sel<<<N_EDGES / 256, 256>>>(edges);                  // 8
    k_agg_init<<<(N_NODES * EMBED) / 256, 256>>>(bg);           // 9
    k_agg_edges<<<(int)(((long long)N_EDGES * 16) / 256), 256>>>(); // 10
    k_final<<<BATCH / 8, 256>>>(x, wl, bl, out);                // 11
}